// round 16
// baseline (speedup 1.0000x reference)
#include <cuda_runtime.h>
#include <cuda_bf16.h>
#include <math.h>
#include <stdint.h>

#define BB 8
#define NN 384
#define DD 512
#define BN (BB * NN)   // 3072
#define SMROW 80       // smem bytes per 32-bf16 row (64B data + 16B pad)

// K1 phase layout
#define K1_SPLIT_N 512
#define K1_B_LR    512      // [512, 896)
#define K1_B_PROJ  896      // [896, 1280)
#define K1_B_AM    1280     // [1280, 1664)
#define K1_TOTAL   1664
// K2 phase layout
#define K2_SCORES_N 288
#define K2_B_FIN    288     // [288, 672)
#define K2_FIN_N    384
#define K2_TOTAL    672

// ---------------- device scratch ----------------
__device__ __nv_bfloat16 g_hh[BN * DD];                   // h bf16
__device__ __nv_bfloat16 g_wqh[DD * DD], g_wkh[DD * DD];  // W bf16
__device__ __nv_bfloat16 g_qh[BN * DD], g_kh[BN * DD];    // q, k bf16
__device__ float g_left[BN], g_right[BN];
__device__ float g_raw[(size_t)BB * NN * NN];

// phase counters (zero-init; reset by K2's last finalize block)
__device__ unsigned g_c_split, g_c_scores, g_c_fin;

// ---------------- helpers ----------------
__device__ __forceinline__ uint32_t smem_u32(const void* p) {
    uint32_t a;
    asm("{ .reg .u64 t; cvta.to.shared.u64 t, %1; cvt.u32.u64 %0, t; }"
        : "=r"(a) : "l"(p));
    return a;
}

__device__ __forceinline__ void cp16(uint32_t dst, const void* src) {
    asm volatile("cp.async.cg.shared.global [%0], [%1], 16;"
                 :: "r"(dst), "l"(src) : "memory");
}
#define CP_COMMIT() asm volatile("cp.async.commit_group;" ::: "memory")

__device__ __forceinline__ void ldsm4(uint32_t* r, uint32_t addr) {
    asm volatile("ldmatrix.sync.aligned.m8n8.x4.shared.b16 {%0,%1,%2,%3}, [%4];"
                 : "=r"(r[0]), "=r"(r[1]), "=r"(r[2]), "=r"(r[3]) : "r"(addr));
}

__device__ __forceinline__ void mma16816(float* c, const uint32_t* a, const uint32_t* b) {
    asm volatile(
        "mma.sync.aligned.m16n8k16.row.col.f32.bf16.bf16.f32 "
        "{%0,%1,%2,%3}, {%4,%5,%6,%7}, {%8,%9}, {%0,%1,%2,%3};"
        : "+f"(c[0]), "+f"(c[1]), "+f"(c[2]), "+f"(c[3])
        : "r"(a[0]), "r"(a[1]), "r"(a[2]), "r"(a[3]), "r"(b[0]), "r"(b[1]));
}

__device__ __forceinline__ void phase_arrive(unsigned* cnt) {
    __threadfence();
    __syncthreads();
    if (threadIdx.x == 0) atomicAdd(cnt, 1u);
}

__device__ __forceinline__ void phase_gate(unsigned* cnt, unsigned target) {
    if (threadIdx.x == 0) {
        volatile unsigned* p = cnt;
        while (*p < target) __nanosleep(64);
    }
    __syncthreads();
    __threadfence();
}

// ---------------------------------------------------------------------------
// Plain bf16 GEMM core: C += A * B^T.
// Tile M = MW*MF*16, N = NW*NF*8, K = 512 in 16 chunks of 32.
// ---------------------------------------------------------------------------
template<int MW, int NW, int MF, int NF, int STAGES>
__device__ __forceinline__ void gemm1(
    const __nv_bfloat16* __restrict__ A,
    const __nv_bfloat16* __restrict__ B,
    char* smem, float acc[MF][NF][4])
{
    constexpr int MT = MW * MF * 16;
    constexpr int NT = NW * NF * 8;
    constexpr int A_BYTES = MT * SMROW;
    constexpr int B_BYTES = NT * SMROW;
    constexpr int STAGE = A_BYTES + B_BYTES;
    constexpr int NTHR = MW * NW * 32;

    const int tid = threadIdx.x;
    const int wid = tid >> 5, lane = tid & 31;
    const int wm = wid % MW, wn = wid / MW;
    const uint32_t s0 = smem_u32(smem);

    const uint32_t a_off = (uint32_t)(lane & 15) * SMROW + (uint32_t)(lane >> 4) * 16;
    const uint32_t b_off = (uint32_t)((lane & 7) + ((lane >> 4) << 3)) * SMROW
                         + (uint32_t)((lane >> 3) & 1) * 16;

    auto issue = [&](int cc) {
        const int k0 = cc * 32;
        const uint32_t sb = s0 + (cc % STAGES) * STAGE;
#pragma unroll
        for (int idx = tid; idx < MT * 4; idx += NTHR) {
            const int r = idx >> 2, g = idx & 3;
            cp16(sb + (uint32_t)r * SMROW + g * 16,
                 A + (size_t)r * DD + k0 + g * 8);
        }
#pragma unroll
        for (int idx = tid; idx < NT * 4; idx += NTHR) {
            const int r = idx >> 2, g = idx & 3;
            cp16(sb + A_BYTES + (uint32_t)r * SMROW + g * 16,
                 B + (size_t)r * DD + k0 + g * 8);
        }
        CP_COMMIT();
    };

#pragma unroll
    for (int p = 0; p < STAGES - 1; p++) issue(p);

#pragma unroll 1
    for (int c = 0; c < 16; c++) {
        if (c + STAGES - 1 < 16) issue(c + STAGES - 1);

        const int rem = 15 - c;
        const int ahead = rem < (STAGES - 1) ? rem : (STAGES - 1);
        if      (ahead <= 0) asm volatile("cp.async.wait_group 0;" ::: "memory");
        else if (ahead == 1) asm volatile("cp.async.wait_group 1;" ::: "memory");
        else if (ahead == 2) asm volatile("cp.async.wait_group 2;" ::: "memory");
        else                 asm volatile("cp.async.wait_group 3;" ::: "memory");
        __syncthreads();

        const uint32_t sb = s0 + (c % STAGES) * STAGE;
#pragma unroll
        for (int ks = 0; ks < 2; ks++) {
            const uint32_t kb = ks * 32;
            uint32_t ahf[MF][4];
#pragma unroll
            for (int mf = 0; mf < MF; mf++) {
                const uint32_t rb = (uint32_t)(wm * MF * 16 + mf * 16) * SMROW + kb + a_off;
                ldsm4(ahf[mf], sb + rb);
            }
#pragma unroll
            for (int np = 0; np < NF / 2; np++) {
                const uint32_t nb = (uint32_t)(wn * NF * 8 + np * 16) * SMROW + kb + b_off;
                uint32_t bh[4];
                ldsm4(bh, sb + A_BYTES + nb);
#pragma unroll
                for (int mf = 0; mf < MF; mf++) {
                    mma16816(acc[mf][np * 2],     ahf[mf], bh);
                    mma16816(acc[mf][np * 2 + 1], ahf[mf], bh + 2);
                }
            }
        }
        __syncthreads();
    }
}

// ---------------------------------------------------------------------------
// K1: splits [0,512) -> lr [512,896) -> proj [896,1280) gated -> am [1280,1664)
// ---------------------------------------------------------------------------
__global__ void __launch_bounds__(256) k1_kernel(
    const float* __restrict__ h,
    const float* __restrict__ Wq, const float* __restrict__ Wk,
    const float* __restrict__ bq,
    const float* __restrict__ wlr, const float* __restrict__ blr,
    const float* __restrict__ wrl, const float* __restrict__ brl,
    const float* __restrict__ mask, float* __restrict__ am_out)
{
    extern __shared__ char smem[];
    const int bid = blockIdx.x;
    const int tid = threadIdx.x;

    if (bid < K1_SPLIT_N) {
        // fp32 -> bf16 conversions (h: 384 blocks, Wq: 64, Wk: 64)
        const float* src;
        __nv_bfloat16* dst;
        long base;
        if (bid < 384)      { src = h;  dst = g_hh;  base = (long)bid * 4096; }
        else if (bid < 448) { src = Wq; dst = g_wqh; base = (long)(bid - 384) * 4096; }
        else                { src = Wk; dst = g_wkh; base = (long)(bid - 448) * 4096; }

        const long o = base + (long)tid * 16;
#pragma unroll
        for (int half = 0; half < 2; half++) {
            const long oo = o + half * 8;
            float4 x0 = *(const float4*)(src + oo);
            float4 x1 = *(const float4*)(src + oo + 4);
            float v[8] = {x0.x, x0.y, x0.z, x0.w, x1.x, x1.y, x1.z, x1.w};
            __nv_bfloat162 p[4];
#pragma unroll
            for (int e = 0; e < 4; e++) {
                p[e].x = __float2bfloat16(v[e * 2]);
                p[e].y = __float2bfloat16(v[e * 2 + 1]);
            }
            *(uint4*)(dst + oo) = *(uint4*)p;
        }
        phase_arrive(&g_c_split);
    } else if (bid < K1_B_PROJ) {
        // lr projections: warp per row
        const int row = (bid - K1_B_LR) * 8 + (tid >> 5);
        const int lane = tid & 31;
        const float* hr = h + (size_t)row * DD;
        float sl = 0.f, sr = 0.f;
        for (int d = lane; d < DD; d += 32) {
            float hv = hr[d];
            sl = fmaf(hv, wlr[d], sl);
            sr = fmaf(hv, wrl[d], sr);
        }
#pragma unroll
        for (int o = 16; o; o >>= 1) {
            sl += __shfl_down_sync(0xFFFFFFFFu, sl, o);
            sr += __shfl_down_sync(0xFFFFFFFFu, sr, o);
        }
        if (lane == 0) {
            g_left[row]  = sl + blr[0];
            g_right[row] = sr + brl[0];
        }
    } else if (bid < K1_B_AM) {
        // proj tile (gated on splits). Tile 128x64, 4-stage.
        phase_gate(&g_c_split, K1_SPLIT_N);

        const int t = bid - K1_B_PROJ;     // 0..383
        const int z = t / 192;
        const int rest = t - z * 192;
        const int m0 = (rest >> 3) * 128;
        const int n0 = (rest & 7) * 64;

        const __nv_bfloat16* B = (z ? g_wkh : g_wqh) + (size_t)n0 * DD;

        float acc[2][4][4];
#pragma unroll
        for (int a = 0; a < 2; a++)
#pragma unroll
            for (int f = 0; f < 4; f++)
#pragma unroll
                for (int e = 0; e < 4; e++) acc[a][f][e] = 0.f;

        gemm1<4, 2, 2, 4, 4>(g_hh + (size_t)m0 * DD, B, smem, acc);

        const int wid = tid >> 5, lane = tid & 31;
        const int wm = wid & 3, wn = wid >> 2;
        __nv_bfloat16* out = z ? g_kh : g_qh;

#pragma unroll
        for (int mf = 0; mf < 2; mf++) {
            const int r0 = m0 + wm * 32 + mf * 16 + (lane >> 2);
#pragma unroll
            for (int f = 0; f < 4; f++) {
                const int c = n0 + wn * 32 + f * 8 + (lane & 3) * 2;
                const float b0 = z ? 0.f : __ldg(&bq[c]);
                const float b1 = z ? 0.f : __ldg(&bq[c + 1]);
                __nv_bfloat162 p0, p1;
                p0.x = __float2bfloat16(acc[mf][f][0] + b0);
                p0.y = __float2bfloat16(acc[mf][f][1] + b1);
                p1.x = __float2bfloat16(acc[mf][f][2] + b0);
                p1.y = __float2bfloat16(acc[mf][f][3] + b1);
                *(__nv_bfloat162*)(out + (size_t)r0 * DD + c) = p0;
                *(__nv_bfloat162*)(out + (size_t)(r0 + 8) * DD + c) = p1;
            }
        }
    } else {
        // alignment_mask writes (independent of everything)
        if (am_out) {
            const int wid = tid >> 5, lane = tid & 31;
            const int bi = (bid - K1_B_AM) * 8 + wid;
            const int b = bi / NN;
            const int i = bi - b * NN;
            const float mi = mask[b * NN + i];
            const float* mp = mask + b * NN + lane * 12;
            float mj[12];
            *(float4*)(mj + 0) = *(const float4*)(mp + 0);
            *(float4*)(mj + 4) = *(const float4*)(mp + 4);
            *(float4*)(mj + 8) = *(const float4*)(mp + 8);
            float am[12];
#pragma unroll
            for (int e = 0; e < 12; e++) am[e] = mi * mj[e];
            float* ap = am_out + (size_t)bi * NN + lane * 12;
            *(float4*)(ap + 0) = *(float4*)(am + 0);
            *(float4*)(ap + 4) = *(float4*)(am + 4);
            *(float4*)(ap + 8) = *(float4*)(am + 8);
        }
    }
}

// ---------------------------------------------------------------------------
// K2: scores [0,288) -> finalize [288,672) gated. Last finalize block resets
// all counters for graph-replay safety.
// ---------------------------------------------------------------------------
__global__ void __launch_bounds__(256) k2_kernel(
    const float* __restrict__ mask,
    const float* __restrict__ alpha_p,
    const float* __restrict__ beta_p,
    const float* __restrict__ gamma_p,
    float* __restrict__ r_out)
{
    extern __shared__ char smem[];
    const int bid = blockIdx.x;
    const int tid = threadIdx.x;

    if (bid < K2_SCORES_N) {
        // scores tile 64x64, 4-stage
        const int b    = bid / 36;
        const int rest = bid - b * 36;
        const int m0 = (rest / 6) * 64;
        const int n0 = (rest % 6) * 64;
        const size_t abase = ((size_t)b * NN + m0) * DD;
        const size_t bbase = ((size_t)b * NN + n0) * DD;

        float acc[2][2][4];
#pragma unroll
        for (int a = 0; a < 2; a++)
#pragma unroll
            for (int f = 0; f < 2; f++)
#pragma unroll
                for (int e = 0; e < 4; e++) acc[a][f][e] = 0.f;

        gemm1<2, 4, 2, 2, 4>(g_qh + abase, g_kh + bbase, smem, acc);

        const float alpha = alpha_p[0], beta = beta_p[0], gamma = gamma_p[0];
        const int wid = tid >> 5, lane = tid & 31;
        const int wm = wid & 1, wn = wid >> 1;

#pragma unroll
        for (int mf = 0; mf < 2; mf++) {
            const int rl = m0 + wm * 32 + mf * 16 + (lane >> 2);
#pragma unroll
            for (int rr = 0; rr < 2; rr++) {
                const int i = rl + rr * 8;
                const float lft = g_left[b * NN + i];
                const float rgt = g_right[b * NN + i];
                float* rb = g_raw + ((size_t)b * NN + i) * NN;
#pragma unroll
                for (int f = 0; f < 2; f++) {
                    const int j = n0 + wn * 16 + f * 8 + (lane & 3) * 2;
                    float2 o;
                    {
                        const float dv = (j >= i) ? lft : rgt;
                        float raw = fmaf(alpha, acc[mf][f][rr * 2],
                                         fmaf(beta, dv, gamma));
                        o.x = fminf(fmaxf(raw, -16.f), 14.f);
                    }
                    {
                        const float dv = (j + 1 >= i) ? lft : rgt;
                        float raw = fmaf(alpha, acc[mf][f][rr * 2 + 1],
                                         fmaf(beta, dv, gamma));
                        o.y = fminf(fmaxf(raw, -16.f), 14.f);
                    }
                    *(float2*)(rb + j) = o;
                }
            }
        }
        phase_arrive(&g_c_scores);
    } else {
        // finalize: warp-per-row, 8 rows per 256-thread block (no am writes)
        phase_gate(&g_c_scores, K2_SCORES_N);

        const int wid = tid >> 5;
        const int lane = tid & 31;
        const int bi = (bid - K2_B_FIN) * 8 + wid;
        const int b = bi / NN;
        const int i = bi - b * NN;

        float* Srow = (float*)smem + wid * (NN + 1);

        const float* rawp = g_raw + (size_t)bi * NN + lane * 12;
        float raw[12];
        *(float4*)(raw + 0) = *(const float4*)(rawp + 0);
        *(float4*)(raw + 4) = *(const float4*)(rawp + 4);
        *(float4*)(raw + 8) = *(const float4*)(rawp + 8);

        float l1[12], pre[12];
        float run = 0.f;
#pragma unroll
        for (int e = 0; e < 12; e++) {
            l1[e] = -__logf(1.f + __expf(raw[e]));
            run += l1[e];
            pre[e] = run;
        }

        float x = run;
#pragma unroll
        for (int o = 1; o < 32; o <<= 1) {
            float y = __shfl_up_sync(0xFFFFFFFFu, x, o);
            if (lane >= o) x += y;
        }
        const float base = x - run;

        if (lane == 0) Srow[0] = 0.f;
#pragma unroll
        for (int e = 0; e < 12; e++)
            Srow[lane * 12 + e + 1] = base + pre[e];
        __syncwarp();

        float r[12];
#pragma unroll
        for (int e = 0; e < 12; e++) {
            const int j = lane * 12 + e;
            const float lp = raw[e] + l1[e];
            float a;
            if (i == j) {
                a = lp - 10000.f;
            } else if (i < j) {
                const int lo = max(2 * i - j + 1, 0);
                a = lp + (Srow[j] - Srow[i + 1]) + (Srow[i] - Srow[lo]);
            } else {
                const int hi = min(2 * i - j, NN - 1);
                a = lp + (Srow[i] - Srow[j + 1]) + (Srow[hi + 1] - Srow[i + 1]);
            }
            r[e] = a;
        }

        float* rp = r_out + (size_t)bi * NN + lane * 12;
        *(float4*)(rp + 0) = *(float4*)(r + 0);
        *(float4*)(rp + 4) = *(float4*)(r + 4);
        *(float4*)(rp + 8) = *(float4*)(r + 8);

        // arrive + last-block counter reset (graph replay safety)
        __threadfence();
        __syncthreads();
        if (tid == 0) {
            const unsigned v = atomicAdd(&g_c_fin, 1u);
            if (v == K2_FIN_N - 1) {
                g_c_split = 0; g_c_scores = 0; g_c_fin = 0;
                __threadfence();
            }
        }
    }
}

// ---------------------------------------------------------------------------
// Launch
// ---------------------------------------------------------------------------
extern "C" void kernel_launch(void* const* d_in, const int* in_sizes, int n_in,
                              void* d_out, int out_size)
{
    const float* h     = (const float*)d_in[0];
    const float* mask  = (const float*)d_in[1];
    const float* Wq    = (const float*)d_in[2];
    const float* bq    = (const float*)d_in[3];
    const float* Wk    = (const float*)d_in[4];
    const float* wlr   = (const float*)d_in[5];
    const float* blr   = (const float*)d_in[6];
    const float* wrl   = (const float*)d_in[7];
    const float* brl   = (const float*)d_in[8];
    const float* alpha = (const float*)d_in[9];
    const float* beta  = (const float*)d_in[10];
    const float* gamma = (const float*)d_in[11];

    float* r_out = (float*)d_out;
    const long long BNN = (long long)BB * NN * NN;
    float* am_out = (out_size >= 2 * BNN) ? (r_out + BNN) : nullptr;

    // K1: proj stage (128 + 64)*80 = 15360 B * 4 = 61440 B (3 CTAs/SM)
    // K2: max(scores 4*10240 = 40960, finalize 8*(NN+1)*4 = 12320) = 40960
    static bool attr_set = false;
    const int k1_smem = 61440, k2_smem = 40960;
    if (!attr_set) {
        cudaFuncSetAttribute(k1_kernel,
                             cudaFuncAttributeMaxDynamicSharedMemorySize, k1_smem);
        cudaFuncSetAttribute(k2_kernel,
                             cudaFuncAttributeMaxDynamicSharedMemorySize, k2_smem);
        attr_set = true;
    }

    k1_kernel<<<K1_TOTAL, 256, k1_smem>>>(h, Wq, Wk, bq, wlr, blr, wrl, brl,
                                          mask, am_out);
    k2_kernel<<<K2_TOTAL, 256, k2_smem>>>(mask, alpha, beta, gamma, r_out);
}